// round 6
// baseline (speedup 1.0000x reference)
#include <cuda_runtime.h>

#define BB 4
#define TSZ 1024
#define DD 512
#define PP 64
#define MM 256

// Scratch (static device memory; no allocation at runtime)
__device__ float g_a1[BB * TSZ * PP];            // x@W1 + b1 + w3e   (t-side)
__device__ float g_a2[BB * TSZ * PP];            // x@W2 + b2         (u-side)
__device__ float g_w3e[BB * PP];                 // ec@W3 + b3
__device__ float g_att[(size_t)BB * TSZ * TSZ];  // scores -> probs (16 MB)

// tanh(x) = 1 - 2/(1+exp(2x)); full-range safe (inf->1, 0->-1), ~1e-7 abs err
__device__ __forceinline__ float fast_tanh(float x) {
    float e, r;
    asm("ex2.approx.f32 %0, %1;" : "=f"(e) : "f"(x * 2.8853900817779268f));
    asm("rcp.approx.f32 %0, %1;" : "=f"(r) : "f"(e + 1.0f));
    return fmaf(-2.0f, r, 1.0f);
}

// ---------------------------------------------------------------- K0: w3e
__global__ void k0_w3e(const float* __restrict__ ec,
                       const float* __restrict__ W3,
                       const float* __restrict__ b3) {
    int tid = threadIdx.x;            // 256 threads: (b,p)
    int b = tid >> 6, p = tid & 63;
    float s = b3[p];
    const float* e = ec + b * MM;
#pragma unroll 8
    for (int m = 0; m < MM; m++) s = fmaf(e[m], W3[m * PP + p], s);
    g_w3e[tid] = s;
}

// ------------------------------------------------- K1: fused projections
// C1 = X@W1 (+b1 +w3e), C2 = X@W2 (+b2); X is (4096 x 512), W (512 x 64)
__global__ __launch_bounds__(256) void k1_proj(const float* __restrict__ x,
                                               const float* __restrict__ W1,
                                               const float* __restrict__ b1,
                                               const float* __restrict__ W2,
                                               const float* __restrict__ b2) {
    __shared__ float XsT[32][68];
    __shared__ float W1s[32][64];
    __shared__ float W2s[32][64];
    int tid = threadIdx.x;
    int r0 = blockIdx.x * 64;
    int tx = tid & 15, ty = tid >> 4;
    float acc1[4][4] = {}, acc2[4][4] = {};

    for (int k0 = 0; k0 < DD; k0 += 32) {
        __syncthreads();
#pragma unroll
        for (int s = 0; s < 2; s++) {
            int f = tid + 256 * s;
            int row = f >> 3, q = f & 7;
            float4 v = *(const float4*)(x + (size_t)(r0 + row) * DD + k0 + q * 4);
            XsT[q * 4 + 0][row] = v.x;
            XsT[q * 4 + 1][row] = v.y;
            XsT[q * 4 + 2][row] = v.z;
            XsT[q * 4 + 3][row] = v.w;
        }
        // W tiles: 32 rows x 64 cols = 512 float4 -> two passes of 256
#pragma unroll
        for (int s = 0; s < 2; s++) {
            int row = (tid >> 4) + 16 * s;
            int q = tid & 15;
            *(float4*)&W1s[row][q * 4] =
                *(const float4*)(W1 + (size_t)(k0 + row) * PP + q * 4);
            *(float4*)&W2s[row][q * 4] =
                *(const float4*)(W2 + (size_t)(k0 + row) * PP + q * 4);
        }
        __syncthreads();
#pragma unroll
        for (int kk = 0; kk < 32; kk++) {
            float4 a = *(float4*)&XsT[kk][ty * 4];
            float4 u = *(float4*)&W1s[kk][tx * 4];
            float4 w = *(float4*)&W2s[kk][tx * 4];
            float av[4] = {a.x, a.y, a.z, a.w};
            float uv[4] = {u.x, u.y, u.z, u.w};
            float wv[4] = {w.x, w.y, w.z, w.w};
#pragma unroll
            for (int i = 0; i < 4; i++)
#pragma unroll
                for (int j = 0; j < 4; j++) {
                    acc1[i][j] = fmaf(av[i], uv[j], acc1[i][j]);
                    acc2[i][j] = fmaf(av[i], wv[j], acc2[i][j]);
                }
        }
    }
    int b = r0 >> 10;
    float4 vb1 = *(const float4*)(b1 + tx * 4);
    float4 vb2 = *(const float4*)(b2 + tx * 4);
    float4 v3 = *(const float4*)(g_w3e + b * PP + tx * 4);
#pragma unroll
    for (int i = 0; i < 4; i++) {
        int row = r0 + ty * 4 + i;
        float4 o1, o2;
        o1.x = acc1[i][0] + vb1.x + v3.x;
        o1.y = acc1[i][1] + vb1.y + v3.y;
        o1.z = acc1[i][2] + vb1.z + v3.z;
        o1.w = acc1[i][3] + vb1.w + v3.w;
        o2.x = acc2[i][0] + vb2.x;
        o2.y = acc2[i][1] + vb2.y;
        o2.z = acc2[i][2] + vb2.z;
        o2.w = acc2[i][3] + vb2.w;
        *(float4*)(g_a1 + (size_t)row * PP + tx * 4) = o1;
        *(float4*)(g_a2 + (size_t)row * PP + tx * 4) = o2;
    }
}

// ---------------------------------------------- K2: attention scores (MUFU-bound)
// at[b,t,u] = sum_p wa[p] * tanh(a1[b,t,p] + a2[b,u,p])
__global__ __launch_bounds__(256) void k2_scores(const float* __restrict__ wa) {
    __shared__ float As[32][65];
    __shared__ float Bs[32][65];
    __shared__ float was[64];
    int tid = threadIdx.x;
    int b = blockIdx.z, t0 = blockIdx.y * 32, u0 = blockIdx.x * 32;
    const float* slabA = g_a1 + (size_t)(b * TSZ + t0) * PP;
    const float* slabB = g_a2 + (size_t)(b * TSZ + u0) * PP;
#pragma unroll
    for (int s = 0; s < 8; s++) {
        int f = tid + 256 * s;
        As[f >> 6][f & 63] = slabA[f];
        Bs[f >> 6][f & 63] = slabB[f];
    }
    if (tid < 64) was[tid] = wa[tid];
    __syncthreads();

    int tu = tid & 15, tt = tid >> 4;
    float a00 = 0.f, a01 = 0.f, a10 = 0.f, a11 = 0.f;
#pragma unroll 8
    for (int p = 0; p < 64; p++) {
        float w = was[p];
        float x0 = As[tt][p], x1 = As[tt + 16][p];
        float y0 = Bs[tu][p], y1 = Bs[tu + 16][p];
        a00 = fmaf(w, fast_tanh(x0 + y0), a00);
        a01 = fmaf(w, fast_tanh(x0 + y1), a01);
        a10 = fmaf(w, fast_tanh(x1 + y0), a10);
        a11 = fmaf(w, fast_tanh(x1 + y1), a11);
    }
    // wa_b is constant across u -> cancels in softmax, skipped.
    float* o0 = g_att + ((size_t)(b * TSZ + t0 + tt)) * TSZ + u0;
    float* o1 = g_att + ((size_t)(b * TSZ + t0 + tt + 16)) * TSZ + u0;
    o0[tu] = a00;
    o0[tu + 16] = a01;
    o1[tu] = a10;
    o1[tu + 16] = a11;
}

// ---------------------------------------------------------------- K3: softmax
__global__ __launch_bounds__(256) void k3_softmax() {
    int row = blockIdx.x;  // flat (b*T + t)
    float* p = g_att + (size_t)row * TSZ;
    int tid = threadIdx.x;
    float v0 = p[tid], v1 = p[tid + 256], v2 = p[tid + 512], v3 = p[tid + 768];
    float m = fmaxf(fmaxf(v0, v1), fmaxf(v2, v3));
#pragma unroll
    for (int o = 16; o; o >>= 1) m = fmaxf(m, __shfl_xor_sync(0xffffffffu, m, o));
    __shared__ float red[8];
    __shared__ float bc[2];
    if ((tid & 31) == 0) red[tid >> 5] = m;
    __syncthreads();
    if (tid == 0) {
        float mm = red[0];
#pragma unroll
        for (int i = 1; i < 8; i++) mm = fmaxf(mm, red[i]);
        bc[0] = mm;
    }
    __syncthreads();
    m = bc[0];
    const float L2E = 1.4426950408889634f;
    float e0, e1, e2, e3;
    asm("ex2.approx.f32 %0, %1;" : "=f"(e0) : "f"((v0 - m) * L2E));
    asm("ex2.approx.f32 %0, %1;" : "=f"(e1) : "f"((v1 - m) * L2E));
    asm("ex2.approx.f32 %0, %1;" : "=f"(e2) : "f"((v2 - m) * L2E));
    asm("ex2.approx.f32 %0, %1;" : "=f"(e3) : "f"((v3 - m) * L2E));
    float s = e0 + e1 + e2 + e3;
#pragma unroll
    for (int o = 16; o; o >>= 1) s += __shfl_xor_sync(0xffffffffu, s, o);
    if ((tid & 31) == 0) red[tid >> 5] = s;
    __syncthreads();
    if (tid == 0) {
        float ss = 0.f;
#pragma unroll
        for (int i = 0; i < 8; i++) ss += red[i];
        bc[1] = 1.0f / ss;
    }
    __syncthreads();
    float inv = bc[1];
    p[tid] = e0 * inv;
    p[tid + 256] = e1 * inv;
    p[tid + 512] = e2 * inv;
    p[tid + 768] = e3 * inv;
}

// ------------------------------------------- K4: out = probs @ inputs (SGEMM)
// per batch: (1024x1024) @ (1024x512); 128x128 tile, 8x8 microtile, BK=8
__global__ __launch_bounds__(256) void k4_out(const float* __restrict__ x,
                                              float* __restrict__ out) {
    __shared__ float AsT[8][132];
    __shared__ float Bs[8][132];
    int tid = threadIdx.x;
    int b = blockIdx.z;
    int t0 = blockIdx.y * 128;
    int d0 = blockIdx.x * 128;
    int tx = tid & 15, ty = tid >> 4;
    const float* Abase = g_att + (size_t)b * TSZ * TSZ;
    const float* Bbase = x + (size_t)b * TSZ * DD;
    int ar = tid >> 1, aq = tid & 1;   // A: 128 rows x 2 float4
    int br = tid >> 5, bsg = tid & 31; // B: 8 rows x 32 float4
    float acc[8][8] = {};

    float4 pa = *(const float4*)(Abase + (size_t)(t0 + ar) * TSZ + aq * 4);
    float4 pb = *(const float4*)(Bbase + (size_t)br * DD + d0 + bsg * 4);

    for (int kc = 0; kc < TSZ / 8; kc++) {
        __syncthreads();
        AsT[aq * 4 + 0][ar] = pa.x;
        AsT[aq * 4 + 1][ar] = pa.y;
        AsT[aq * 4 + 2][ar] = pa.z;
        AsT[aq * 4 + 3][ar] = pa.w;
        *(float4*)&Bs[br][bsg * 4] = pb;
        __syncthreads();
        if (kc + 1 < TSZ / 8) {
            int k0 = (kc + 1) * 8;
            pa = *(const float4*)(Abase + (size_t)(t0 + ar) * TSZ + k0 + aq * 4);
            pb = *(const float4*)(Bbase + (size_t)(k0 + br) * DD + d0 + bsg * 4);
        }
#pragma unroll
        for (int kk = 0; kk < 8; kk++) {
            float4 a0 = *(float4*)&AsT[kk][ty * 4];
            float4 a1 = *(float4*)&AsT[kk][64 + ty * 4];
            float4 b0 = *(float4*)&Bs[kk][tx * 4];
            float4 b1 = *(float4*)&Bs[kk][64 + tx * 4];
            float av[8] = {a0.x, a0.y, a0.z, a0.w, a1.x, a1.y, a1.z, a1.w};
            float bv[8] = {b0.x, b0.y, b0.z, b0.w, b1.x, b1.y, b1.z, b1.w};
#pragma unroll
            for (int i = 0; i < 8; i++)
#pragma unroll
                for (int j = 0; j < 8; j++)
                    acc[i][j] = fmaf(av[i], bv[j], acc[i][j]);
        }
    }
#pragma unroll
    for (int i = 0; i < 8; i++) {
        int row = t0 + ((i < 4) ? (ty * 4 + i) : (64 + ty * 4 + i - 4));
        float* orow = out + (size_t)(b * TSZ + row) * DD + d0;
        float4 v0 = make_float4(acc[i][0], acc[i][1], acc[i][2], acc[i][3]);
        float4 v1 = make_float4(acc[i][4], acc[i][5], acc[i][6], acc[i][7]);
        *(float4*)(orow + tx * 4) = v0;
        *(float4*)(orow + 64 + tx * 4) = v1;
    }
}

extern "C" void kernel_launch(void* const* d_in, const int* in_sizes, int n_in,
                              void* d_out, int out_size) {
    const float* x = (const float*)d_in[0];
    const float* ec = (const float*)d_in[1];
    const float* W1 = (const float*)d_in[2];
    const float* b1 = (const float*)d_in[3];
    const float* W2 = (const float*)d_in[4];
    const float* b2 = (const float*)d_in[5];
    const float* W3 = (const float*)d_in[6];
    const float* b3 = (const float*)d_in[7];
    const float* wa = (const float*)d_in[8];
    // d_in[9] = wa_b: constant over u, cancels inside softmax -> unused.
    float* out = (float*)d_out;

    k0_w3e<<<1, 256>>>(ec, W3, b3);
    k1_proj<<<64, 256>>>(x, W1, b1, W2, b2);
    k2_scores<<<dim3(32, 32, 4), 256>>>(wa);
    k3_softmax<<<4096, 256>>>();
    k4_out<<<dim3(4, 8, 4), 256>>>(x, out);
}

// round 8
// speedup vs baseline: 1.2761x; 1.2761x over previous
#include <cuda_runtime.h>

#define BB 4
#define TSZ 1024
#define DD 512
#define PP 64
#define MM 256

// Scratch (static device memory; no allocation at runtime)
__device__ float g_a1[BB * TSZ * PP];            // x@W1 + b1 + w3e   (t-side)
__device__ float g_a2[BB * TSZ * PP];            // x@W2 + b2         (u-side)
__device__ float g_w3e[BB * PP];                 // ec@W3 + b3
__device__ float g_att[(size_t)BB * TSZ * TSZ];  // scores -> probs (16 MB)

// single-MUFU tanh (MUFU.TANH), abs err ~2^-11 -> final rel_err ~1e-4 < 1e-3
__device__ __forceinline__ float fast_tanh(float x) {
    float y;
    asm("tanh.approx.f32 %0, %1;" : "=f"(y) : "f"(x));
    return y;
}

// ---------------------------------------------------------------- K0: w3e
__global__ void k0_w3e(const float* __restrict__ ec,
                       const float* __restrict__ W3,
                       const float* __restrict__ b3) {
    int tid = threadIdx.x;            // 256 threads: (b,p)
    int b = tid >> 6, p = tid & 63;
    float s = b3[p];
    const float* e = ec + b * MM;
#pragma unroll 8
    for (int m = 0; m < MM; m++) s = fmaf(e[m], W3[m * PP + p], s);
    g_w3e[tid] = s;
}

// ------------------------------------------------- K1: fused projections
// C1 = X@W1 (+b1 +w3e), C2 = X@W2 (+b2); X is (4096 x 512), W (512 x 64)
__global__ __launch_bounds__(256) void k1_proj(const float* __restrict__ x,
                                               const float* __restrict__ W1,
                                               const float* __restrict__ b1,
                                               const float* __restrict__ W2,
                                               const float* __restrict__ b2) {
    __shared__ float XsT[32][68];
    __shared__ float W1s[32][64];
    __shared__ float W2s[32][64];
    int tid = threadIdx.x;
    int r0 = blockIdx.x * 64;
    int tx = tid & 15, ty = tid >> 4;
    float acc1[4][4] = {}, acc2[4][4] = {};

    for (int k0 = 0; k0 < DD; k0 += 32) {
        __syncthreads();
#pragma unroll
        for (int s = 0; s < 2; s++) {
            int f = tid + 256 * s;
            int row = f >> 3, q = f & 7;
            float4 v = *(const float4*)(x + (size_t)(r0 + row) * DD + k0 + q * 4);
            XsT[q * 4 + 0][row] = v.x;
            XsT[q * 4 + 1][row] = v.y;
            XsT[q * 4 + 2][row] = v.z;
            XsT[q * 4 + 3][row] = v.w;
        }
#pragma unroll
        for (int s = 0; s < 2; s++) {
            int row = (tid >> 4) + 16 * s;
            int q = tid & 15;
            *(float4*)&W1s[row][q * 4] =
                *(const float4*)(W1 + (size_t)(k0 + row) * PP + q * 4);
            *(float4*)&W2s[row][q * 4] =
                *(const float4*)(W2 + (size_t)(k0 + row) * PP + q * 4);
        }
        __syncthreads();
#pragma unroll
        for (int kk = 0; kk < 32; kk++) {
            float4 a = *(float4*)&XsT[kk][ty * 4];
            float4 u = *(float4*)&W1s[kk][tx * 4];
            float4 w = *(float4*)&W2s[kk][tx * 4];
            float av[4] = {a.x, a.y, a.z, a.w};
            float uv[4] = {u.x, u.y, u.z, u.w};
            float wv[4] = {w.x, w.y, w.z, w.w};
#pragma unroll
            for (int i = 0; i < 4; i++)
#pragma unroll
                for (int j = 0; j < 4; j++) {
                    acc1[i][j] = fmaf(av[i], uv[j], acc1[i][j]);
                    acc2[i][j] = fmaf(av[i], wv[j], acc2[i][j]);
                }
        }
    }
    int b = r0 >> 10;
    float4 vb1 = *(const float4*)(b1 + tx * 4);
    float4 vb2 = *(const float4*)(b2 + tx * 4);
    float4 v3 = *(const float4*)(g_w3e + b * PP + tx * 4);
#pragma unroll
    for (int i = 0; i < 4; i++) {
        int row = r0 + ty * 4 + i;
        float4 o1, o2;
        o1.x = acc1[i][0] + vb1.x + v3.x;
        o1.y = acc1[i][1] + vb1.y + v3.y;
        o1.z = acc1[i][2] + vb1.z + v3.z;
        o1.w = acc1[i][3] + vb1.w + v3.w;
        o2.x = acc2[i][0] + vb2.x;
        o2.y = acc2[i][1] + vb2.y;
        o2.z = acc2[i][2] + vb2.z;
        o2.w = acc2[i][3] + vb2.w;
        *(float4*)(g_a1 + (size_t)row * PP + tx * 4) = o1;
        *(float4*)(g_a2 + (size_t)row * PP + tx * 4) = o2;
    }
}

// ---------------------------------------------- K2: attention scores (MUFU-bound)
// at[b,t,u] = sum_p wa[p] * tanh(a1[b,t,p] + a2[b,u,p])
__global__ __launch_bounds__(256) void k2_scores(const float* __restrict__ wa) {
    __shared__ float As[32][65];
    __shared__ float Bs[32][65];
    __shared__ float was[64];
    int tid = threadIdx.x;
    int b = blockIdx.z, t0 = blockIdx.y * 32, u0 = blockIdx.x * 32;
    const float* slabA = g_a1 + (size_t)(b * TSZ + t0) * PP;
    const float* slabB = g_a2 + (size_t)(b * TSZ + u0) * PP;
#pragma unroll
    for (int s = 0; s < 8; s++) {
        int f = tid + 256 * s;
        As[f >> 6][f & 63] = slabA[f];
        Bs[f >> 6][f & 63] = slabB[f];
    }
    if (tid < 64) was[tid] = wa[tid];
    __syncthreads();

    int tu = tid & 15, tt = tid >> 4;
    float a00 = 0.f, a01 = 0.f, a10 = 0.f, a11 = 0.f;
#pragma unroll 8
    for (int p = 0; p < 64; p++) {
        float w = was[p];
        float x0 = As[tt][p], x1 = As[tt + 16][p];
        float y0 = Bs[tu][p], y1 = Bs[tu + 16][p];
        a00 = fmaf(w, fast_tanh(x0 + y0), a00);
        a01 = fmaf(w, fast_tanh(x0 + y1), a01);
        a10 = fmaf(w, fast_tanh(x1 + y0), a10);
        a11 = fmaf(w, fast_tanh(x1 + y1), a11);
    }
    // wa_b is constant across u -> cancels in softmax, skipped.
    float* o0 = g_att + ((size_t)(b * TSZ + t0 + tt)) * TSZ + u0;
    float* o1 = g_att + ((size_t)(b * TSZ + t0 + tt + 16)) * TSZ + u0;
    o0[tu] = a00;
    o0[tu + 16] = a01;
    o1[tu] = a10;
    o1[tu + 16] = a11;
}

// ---------------------------------------------------------------- K3: softmax
__global__ __launch_bounds__(256) void k3_softmax() {
    int row = blockIdx.x;  // flat (b*T + t)
    float* p = g_att + (size_t)row * TSZ;
    int tid = threadIdx.x;
    float v0 = p[tid], v1 = p[tid + 256], v2 = p[tid + 512], v3 = p[tid + 768];
    float m = fmaxf(fmaxf(v0, v1), fmaxf(v2, v3));
#pragma unroll
    for (int o = 16; o; o >>= 1) m = fmaxf(m, __shfl_xor_sync(0xffffffffu, m, o));
    __shared__ float red[8];
    __shared__ float bc[2];
    if ((tid & 31) == 0) red[tid >> 5] = m;
    __syncthreads();
    if (tid == 0) {
        float mm = red[0];
#pragma unroll
        for (int i = 1; i < 8; i++) mm = fmaxf(mm, red[i]);
        bc[0] = mm;
    }
    __syncthreads();
    m = bc[0];
    const float L2E = 1.4426950408889634f;
    float e0, e1, e2, e3;
    asm("ex2.approx.f32 %0, %1;" : "=f"(e0) : "f"((v0 - m) * L2E));
    asm("ex2.approx.f32 %0, %1;" : "=f"(e1) : "f"((v1 - m) * L2E));
    asm("ex2.approx.f32 %0, %1;" : "=f"(e2) : "f"((v2 - m) * L2E));
    asm("ex2.approx.f32 %0, %1;" : "=f"(e3) : "f"((v3 - m) * L2E));
    float s = e0 + e1 + e2 + e3;
#pragma unroll
    for (int o = 16; o; o >>= 1) s += __shfl_xor_sync(0xffffffffu, s, o);
    if ((tid & 31) == 0) red[tid >> 5] = s;
    __syncthreads();
    if (tid == 0) {
        float ss = 0.f;
#pragma unroll
        for (int i = 0; i < 8; i++) ss += red[i];
        bc[1] = 1.0f / ss;
    }
    __syncthreads();
    float inv = bc[1];
    p[tid] = e0 * inv;
    p[tid + 256] = e1 * inv;
    p[tid + 512] = e2 * inv;
    p[tid + 768] = e3 * inv;
}

// ------------------------------------------- K4: out = probs @ inputs (SGEMM)
// per batch: (1024x1024) @ (1024x512); 128x128 tile, 8x8 microtile, BK=8
__global__ __launch_bounds__(256) void k4_out(const float* __restrict__ x,
                                              float* __restrict__ out) {
    __shared__ float AsT[8][132];
    __shared__ float Bs[8][132];
    int tid = threadIdx.x;
    int b = blockIdx.z;
    int t0 = blockIdx.y * 128;
    int d0 = blockIdx.x * 128;
    int tx = tid & 15, ty = tid >> 4;
    const float* Abase = g_att + (size_t)b * TSZ * TSZ;
    const float* Bbase = x + (size_t)b * TSZ * DD;
    int ar = tid >> 1, aq = tid & 1;   // A: 128 rows x 2 float4
    int br = tid >> 5, bsg = tid & 31; // B: 8 rows x 32 float4
    float acc[8][8] = {};

    float4 pa = *(const float4*)(Abase + (size_t)(t0 + ar) * TSZ + aq * 4);
    float4 pb = *(const float4*)(Bbase + (size_t)br * DD + d0 + bsg * 4);

    for (int kc = 0; kc < TSZ / 8; kc++) {
        __syncthreads();
        AsT[aq * 4 + 0][ar] = pa.x;
        AsT[aq * 4 + 1][ar] = pa.y;
        AsT[aq * 4 + 2][ar] = pa.z;
        AsT[aq * 4 + 3][ar] = pa.w;
        *(float4*)&Bs[br][bsg * 4] = pb;
        __syncthreads();
        if (kc + 1 < TSZ / 8) {
            int k0 = (kc + 1) * 8;
            pa = *(const float4*)(Abase + (size_t)(t0 + ar) * TSZ + k0 + aq * 4);
            pb = *(const float4*)(Bbase + (size_t)(k0 + br) * DD + d0 + bsg * 4);
        }
#pragma unroll
        for (int kk = 0; kk < 8; kk++) {
            float4 a0 = *(float4*)&AsT[kk][ty * 4];
            float4 a1 = *(float4*)&AsT[kk][64 + ty * 4];
            float4 b0 = *(float4*)&Bs[kk][tx * 4];
            float4 b1 = *(float4*)&Bs[kk][64 + tx * 4];
            float av[8] = {a0.x, a0.y, a0.z, a0.w, a1.x, a1.y, a1.z, a1.w};
            float bv[8] = {b0.x, b0.y, b0.z, b0.w, b1.x, b1.y, b1.z, b1.w};
#pragma unroll
            for (int i = 0; i < 8; i++)
#pragma unroll
                for (int j = 0; j < 8; j++)
                    acc[i][j] = fmaf(av[i], bv[j], acc[i][j]);
        }
    }
#pragma unroll
    for (int i = 0; i < 8; i++) {
        int row = t0 + ((i < 4) ? (ty * 4 + i) : (64 + ty * 4 + i - 4));
        float* orow = out + (size_t)(b * TSZ + row) * DD + d0;
        float4 v0 = make_float4(acc[i][0], acc[i][1], acc[i][2], acc[i][3]);
        float4 v1 = make_float4(acc[i][4], acc[i][5], acc[i][6], acc[i][7]);
        *(float4*)(orow + tx * 4) = v0;
        *(float4*)(orow + 64 + tx * 4) = v1;
    }
}

extern "C" void kernel_launch(void* const* d_in, const int* in_sizes, int n_in,
                              void* d_out, int out_size) {
    const float* x = (const float*)d_in[0];
    const float* ec = (const float*)d_in[1];
    const float* W1 = (const float*)d_in[2];
    const float* b1 = (const float*)d_in[3];
    const float* W2 = (const float*)d_in[4];
    const float* b2 = (const float*)d_in[5];
    const float* W3 = (const float*)d_in[6];
    const float* b3 = (const float*)d_in[7];
    const float* wa = (const float*)d_in[8];
    // d_in[9] = wa_b: constant over u, cancels inside softmax -> unused.
    float* out = (float*)d_out;

    k0_w3e<<<1, 256>>>(ec, W3, b3);
    k1_proj<<<64, 256>>>(x, W1, b1, W2, b2);
    k2_scores<<<dim3(32, 32, 4), 256>>>(wa);
    k3_softmax<<<4096, 256>>>();
    k4_out<<<dim3(4, 8, 4), 256>>>(x, out);
}

// round 9
// speedup vs baseline: 1.7128x; 1.3422x over previous
#include <cuda_runtime.h>
#include <cuda_bf16.h>
#include <cstdint>

#define BB 4
#define TSZ 1024
#define DD 512
#define PP 64
#define MM 256

// Scratch (static device memory; no allocation at runtime)
__device__ float g_a1[BB * TSZ * PP];            // x@W1 + b1 + w3e   (t-side)
__device__ float g_a2[BB * TSZ * PP];            // x@W2 + b2         (u-side)
__device__ float g_w3e[BB * PP];                 // ec@W3 + b3
__device__ float g_att[(size_t)BB * TSZ * TSZ];  // scores -> probs (16 MB)

// single-MUFU tanh (MUFU.TANH)
__device__ __forceinline__ float fast_tanh(float x) {
    float y;
    asm("tanh.approx.f32 %0, %1;" : "=f"(y) : "f"(x));
    return y;
}

// ---------------------------------------------------------------- K0: w3e
__global__ void k0_w3e(const float* __restrict__ ec,
                       const float* __restrict__ W3,
                       const float* __restrict__ b3) {
    int tid = threadIdx.x;            // 256 threads: (b,p)
    int b = tid >> 6, p = tid & 63;
    float s = b3[p];
    const float* e = ec + b * MM;
#pragma unroll 8
    for (int m = 0; m < MM; m++) s = fmaf(e[m], W3[m * PP + p], s);
    g_w3e[tid] = s;
}

// ------------------------------------------------- K1: fused projections
__global__ __launch_bounds__(256) void k1_proj(const float* __restrict__ x,
                                               const float* __restrict__ W1,
                                               const float* __restrict__ b1,
                                               const float* __restrict__ W2,
                                               const float* __restrict__ b2) {
    __shared__ float XsT[32][68];
    __shared__ float W1s[32][64];
    __shared__ float W2s[32][64];
    int tid = threadIdx.x;
    int r0 = blockIdx.x * 64;
    int tx = tid & 15, ty = tid >> 4;
    float acc1[4][4] = {}, acc2[4][4] = {};

    for (int k0 = 0; k0 < DD; k0 += 32) {
        __syncthreads();
#pragma unroll
        for (int s = 0; s < 2; s++) {
            int f = tid + 256 * s;
            int row = f >> 3, q = f & 7;
            float4 v = *(const float4*)(x + (size_t)(r0 + row) * DD + k0 + q * 4);
            XsT[q * 4 + 0][row] = v.x;
            XsT[q * 4 + 1][row] = v.y;
            XsT[q * 4 + 2][row] = v.z;
            XsT[q * 4 + 3][row] = v.w;
        }
#pragma unroll
        for (int s = 0; s < 2; s++) {
            int row = (tid >> 4) + 16 * s;
            int q = tid & 15;
            *(float4*)&W1s[row][q * 4] =
                *(const float4*)(W1 + (size_t)(k0 + row) * PP + q * 4);
            *(float4*)&W2s[row][q * 4] =
                *(const float4*)(W2 + (size_t)(k0 + row) * PP + q * 4);
        }
        __syncthreads();
#pragma unroll
        for (int kk = 0; kk < 32; kk++) {
            float4 a = *(float4*)&XsT[kk][ty * 4];
            float4 u = *(float4*)&W1s[kk][tx * 4];
            float4 w = *(float4*)&W2s[kk][tx * 4];
            float av[4] = {a.x, a.y, a.z, a.w};
            float uv[4] = {u.x, u.y, u.z, u.w};
            float wv[4] = {w.x, w.y, w.z, w.w};
#pragma unroll
            for (int i = 0; i < 4; i++)
#pragma unroll
                for (int j = 0; j < 4; j++) {
                    acc1[i][j] = fmaf(av[i], uv[j], acc1[i][j]);
                    acc2[i][j] = fmaf(av[i], wv[j], acc2[i][j]);
                }
        }
    }
    int b = r0 >> 10;
    float4 vb1 = *(const float4*)(b1 + tx * 4);
    float4 vb2 = *(const float4*)(b2 + tx * 4);
    float4 v3 = *(const float4*)(g_w3e + b * PP + tx * 4);
#pragma unroll
    for (int i = 0; i < 4; i++) {
        int row = r0 + ty * 4 + i;
        float4 o1, o2;
        o1.x = acc1[i][0] + vb1.x + v3.x;
        o1.y = acc1[i][1] + vb1.y + v3.y;
        o1.z = acc1[i][2] + vb1.z + v3.z;
        o1.w = acc1[i][3] + vb1.w + v3.w;
        o2.x = acc2[i][0] + vb2.x;
        o2.y = acc2[i][1] + vb2.y;
        o2.z = acc2[i][2] + vb2.z;
        o2.w = acc2[i][3] + vb2.w;
        *(float4*)(g_a1 + (size_t)row * PP + tx * 4) = o1;
        *(float4*)(g_a2 + (size_t)row * PP + tx * 4) = o2;
    }
}

// ---------------------------------------------- K2: attention scores (MUFU-bound)
__global__ __launch_bounds__(256) void k2_scores(const float* __restrict__ wa) {
    __shared__ float As[32][65];
    __shared__ float Bs[32][65];
    __shared__ float was[64];
    int tid = threadIdx.x;
    int b = blockIdx.z, t0 = blockIdx.y * 32, u0 = blockIdx.x * 32;
    const float* slabA = g_a1 + (size_t)(b * TSZ + t0) * PP;
    const float* slabB = g_a2 + (size_t)(b * TSZ + u0) * PP;
#pragma unroll
    for (int s = 0; s < 8; s++) {
        int f = tid + 256 * s;
        As[f >> 6][f & 63] = slabA[f];
        Bs[f >> 6][f & 63] = slabB[f];
    }
    if (tid < 64) was[tid] = wa[tid];
    __syncthreads();

    int tu = tid & 15, tt = tid >> 4;
    float a00 = 0.f, a01 = 0.f, a10 = 0.f, a11 = 0.f;
#pragma unroll 8
    for (int p = 0; p < 64; p++) {
        float w = was[p];
        float x0 = As[tt][p], x1 = As[tt + 16][p];
        float y0 = Bs[tu][p], y1 = Bs[tu + 16][p];
        a00 = fmaf(w, fast_tanh(x0 + y0), a00);
        a01 = fmaf(w, fast_tanh(x0 + y1), a01);
        a10 = fmaf(w, fast_tanh(x1 + y0), a10);
        a11 = fmaf(w, fast_tanh(x1 + y1), a11);
    }
    float* o0 = g_att + ((size_t)(b * TSZ + t0 + tt)) * TSZ + u0;
    float* o1 = g_att + ((size_t)(b * TSZ + t0 + tt + 16)) * TSZ + u0;
    o0[tu] = a00;
    o0[tu + 16] = a01;
    o1[tu] = a10;
    o1[tu + 16] = a11;
}

// ---------------------------------------------------------------- K3: softmax
__global__ __launch_bounds__(256) void k3_softmax() {
    int row = blockIdx.x;
    float* p = g_att + (size_t)row * TSZ;
    int tid = threadIdx.x;
    float v0 = p[tid], v1 = p[tid + 256], v2 = p[tid + 512], v3 = p[tid + 768];
    float m = fmaxf(fmaxf(v0, v1), fmaxf(v2, v3));
#pragma unroll
    for (int o = 16; o; o >>= 1) m = fmaxf(m, __shfl_xor_sync(0xffffffffu, m, o));
    __shared__ float red[8];
    __shared__ float bc[2];
    if ((tid & 31) == 0) red[tid >> 5] = m;
    __syncthreads();
    if (tid == 0) {
        float mm = red[0];
#pragma unroll
        for (int i = 1; i < 8; i++) mm = fmaxf(mm, red[i]);
        bc[0] = mm;
    }
    __syncthreads();
    m = bc[0];
    const float L2E = 1.4426950408889634f;
    float e0, e1, e2, e3;
    asm("ex2.approx.f32 %0, %1;" : "=f"(e0) : "f"((v0 - m) * L2E));
    asm("ex2.approx.f32 %0, %1;" : "=f"(e1) : "f"((v1 - m) * L2E));
    asm("ex2.approx.f32 %0, %1;" : "=f"(e2) : "f"((v2 - m) * L2E));
    asm("ex2.approx.f32 %0, %1;" : "=f"(e3) : "f"((v3 - m) * L2E));
    float s = e0 + e1 + e2 + e3;
#pragma unroll
    for (int o = 16; o; o >>= 1) s += __shfl_xor_sync(0xffffffffu, s, o);
    if ((tid & 31) == 0) red[tid >> 5] = s;
    __syncthreads();
    if (tid == 0) {
        float ss = 0.f;
#pragma unroll
        for (int i = 0; i < 8; i++) ss += red[i];
        bc[1] = 1.0f / ss;
    }
    __syncthreads();
    float inv = bc[1];
    p[tid] = e0 * inv;
    p[tid + 256] = e1 * inv;
    p[tid + 512] = e2 * inv;
    p[tid + 768] = e3 * inv;
}

// ============ K4: out = probs @ inputs via mma.sync bf16 3-term split ========
// Block tile 128x128, BK=32; 8 warps in 2(M)x4(N); warp tile 64x32.
// A (probs) and B (x, transposed to [n][k]) stored as bf16 hi/lo SMEM tiles,
// row stride 80B + XOR swizzle on bits[4:5] by (row>>3)&3 -> conflict-free
// ldmatrix; D accumulated fp32 in HMMA.

__device__ __forceinline__ uint32_t smem_u32(const void* p) {
    uint32_t a;
    asm("{ .reg .u64 t; cvta.to.shared.u64 t, %1; cvt.u32.u64 %0, t; }"
        : "=r"(a) : "l"(p));
    return a;
}
__device__ __forceinline__ uint32_t swz(uint32_t row, uint32_t byteoff) {
    return row * 80u + (byteoff ^ ((row & 24u) << 1));
}
__device__ __forceinline__ uint32_t pack_bf16(float lo, float hi) {
    __nv_bfloat162 t = __floats2bfloat162_rn(lo, hi);  // .x = lo (low 16 bits)
    return *(uint32_t*)&t;
}
__device__ __forceinline__ void bsplit(float v, float& h, float& l) {
    float hh = __bfloat162float(__float2bfloat16_rn(v));
    h = hh;
    l = v - hh;
}
__device__ __forceinline__ void ldsm4(uint32_t r[4], uint32_t addr) {
    asm volatile(
        "ldmatrix.sync.aligned.m8n8.x4.shared.b16 {%0,%1,%2,%3}, [%4];"
        : "=r"(r[0]), "=r"(r[1]), "=r"(r[2]), "=r"(r[3]) : "r"(addr));
}
__device__ __forceinline__ void mma_bf16(float c[4], const uint32_t a[4],
                                         uint32_t b0, uint32_t b1) {
    asm volatile(
        "mma.sync.aligned.m16n8k16.row.col.f32.bf16.bf16.f32 "
        "{%0,%1,%2,%3}, {%4,%5,%6,%7}, {%8,%9}, {%0,%1,%2,%3};"
        : "+f"(c[0]), "+f"(c[1]), "+f"(c[2]), "+f"(c[3])
        : "r"(a[0]), "r"(a[1]), "r"(a[2]), "r"(a[3]), "r"(b0), "r"(b1));
}

__global__ __launch_bounds__(256) void k4_out_mma(const float* __restrict__ x,
                                                  float* __restrict__ out) {
    __shared__ uint8_t smAh[128 * 80];
    __shared__ uint8_t smAl[128 * 80];
    __shared__ uint8_t smBh[128 * 80];
    __shared__ uint8_t smBl[128 * 80];
    uint32_t baseAh = smem_u32(smAh), baseAl = smem_u32(smAl);
    uint32_t baseBh = smem_u32(smBh), baseBl = smem_u32(smBl);

    int tid = threadIdx.x, wid = tid >> 5, lane = tid & 31;
    int b = blockIdx.z, t0 = blockIdx.y * 128, d0 = blockIdx.x * 128;
    int warp_m = wid >> 2, warp_n = wid & 3;

    const float* Abase = g_att + (size_t)b * TSZ * TSZ + (size_t)t0 * TSZ;
    const float* Bbase = x + (size_t)b * TSZ * DD;

    // prefetch indices
    int arow = tid >> 3, aq = tid & 7;       // A: row 0..127, float4 index 0..7
    int bc_ = wid >> 2, bn = (wid & 3) * 32 + lane;  // B: k-half, n-column

    float acc[4][4][4] = {};
    float pa[16], pb[16];

    // prefetch chunk 0
#pragma unroll
    for (int s = 0; s < 4; s++) {
        float4 v = *(const float4*)(Abase + (size_t)arow * TSZ + (s * 8 + aq) * 4);
        // note: with 256 threads, (tid+256s)>>3 = arow + 32s? No: keep mapping
        pa[s * 4 + 0] = v.x; pa[s * 4 + 1] = v.y;
        pa[s * 4 + 2] = v.z; pa[s * 4 + 3] = v.w;
    }
    // fix A mapping: thread handles rows arow, arow+32, arow+64, arow+96 at q=aq
    // (re-done below properly; the loop above is replaced)
#pragma unroll
    for (int s = 0; s < 4; s++) {
        float4 v = *(const float4*)(Abase + (size_t)(arow + 32 * s) * TSZ + aq * 4);
        pa[s * 4 + 0] = v.x; pa[s * 4 + 1] = v.y;
        pa[s * 4 + 2] = v.z; pa[s * 4 + 3] = v.w;
    }
#pragma unroll
    for (int j = 0; j < 16; j++)
        pb[j] = Bbase[(size_t)(bc_ * 16 + j) * DD + d0 + bn];

    int mi = lane >> 3, r8 = lane & 7;
    uint32_t a_rb = warp_m * 64 + (mi & 1) * 8 + r8;   // A frag row within tile
    uint32_t a_kb0 = (mi >> 1) * 16;                   // A frag k-byte within kstep
    uint32_t b_rb = warp_n * 32 + ((mi >> 1) & 1) * 8 + r8;
    uint32_t b_kb0 = (mi & 1) * 16;

    for (int ch = 0; ch < 32; ch++) {
        __syncthreads();
        // store prefetched regs -> smem (bf16 hi/lo, swizzled)
#pragma unroll
        for (int s = 0; s < 4; s++) {
            int row = arow + 32 * s;
            float h0, h1, h2, h3, l0, l1, l2, l3;
            bsplit(pa[s * 4 + 0], h0, l0);
            bsplit(pa[s * 4 + 1], h1, l1);
            bsplit(pa[s * 4 + 2], h2, l2);
            bsplit(pa[s * 4 + 3], h3, l3);
            uint32_t ad = swz(row, aq * 8u);
            uint32_t ph0 = pack_bf16(h0, h1), ph1 = pack_bf16(h2, h3);
            uint32_t pl0 = pack_bf16(l0, l1), pl1 = pack_bf16(l2, l3);
            asm volatile("st.shared.v2.b32 [%0], {%1,%2};"
                         :: "r"(baseAh + ad), "r"(ph0), "r"(ph1) : "memory");
            asm volatile("st.shared.v2.b32 [%0], {%1,%2};"
                         :: "r"(baseAl + ad), "r"(pl0), "r"(pl1) : "memory");
        }
#pragma unroll
        for (int j = 0; j < 16; j += 4) {
            float h0, h1, h2, h3, l0, l1, l2, l3;
            bsplit(pb[j + 0], h0, l0);
            bsplit(pb[j + 1], h1, l1);
            bsplit(pb[j + 2], h2, l2);
            bsplit(pb[j + 3], h3, l3);
            uint32_t bd = swz(bn, (bc_ * 16 + j) * 2u);
            uint32_t ph0 = pack_bf16(h0, h1), ph1 = pack_bf16(h2, h3);
            uint32_t pl0 = pack_bf16(l0, l1), pl1 = pack_bf16(l2, l3);
            asm volatile("st.shared.v2.b32 [%0], {%1,%2};"
                         :: "r"(baseBh + bd), "r"(ph0), "r"(ph1) : "memory");
            asm volatile("st.shared.v2.b32 [%0], {%1,%2};"
                         :: "r"(baseBl + bd), "r"(pl0), "r"(pl1) : "memory");
        }
        __syncthreads();
        // issue next-chunk global loads (overlap with mma phase)
        if (ch + 1 < 32) {
            int k0 = (ch + 1) * 32;
#pragma unroll
            for (int s = 0; s < 4; s++) {
                float4 v = *(const float4*)(Abase + (size_t)(arow + 32 * s) * TSZ +
                                            k0 + aq * 4);
                pa[s * 4 + 0] = v.x; pa[s * 4 + 1] = v.y;
                pa[s * 4 + 2] = v.z; pa[s * 4 + 3] = v.w;
            }
#pragma unroll
            for (int j = 0; j < 16; j++)
                pb[j] = Bbase[(size_t)(k0 + bc_ * 16 + j) * DD + d0 + bn];
        }
        // mma phase: 2 k-steps of k16
#pragma unroll
        for (int ks = 0; ks < 2; ks++) {
            uint32_t Ah[4][4], Al[4][4], Bh[2][4], Bl[2][4];
            uint32_t akb = ks * 32u + a_kb0;
            uint32_t bkb = ks * 32u + b_kb0;
#pragma unroll
            for (int mt = 0; mt < 4; mt++) {
                uint32_t ad = swz(a_rb + mt * 16, akb);
                ldsm4(Ah[mt], baseAh + ad);
                ldsm4(Al[mt], baseAl + ad);
            }
#pragma unroll
            for (int np = 0; np < 2; np++) {
                uint32_t bd = swz(b_rb + np * 16, bkb);
                ldsm4(Bh[np], baseBh + bd);
                ldsm4(Bl[np], baseBl + bd);
            }
#pragma unroll
            for (int mt = 0; mt < 4; mt++)
#pragma unroll
                for (int np = 0; np < 2; np++)
#pragma unroll
                    for (int hf = 0; hf < 2; hf++) {
                        int nt = np * 2 + hf;
                        uint32_t bh0 = Bh[np][hf * 2], bh1 = Bh[np][hf * 2 + 1];
                        uint32_t bl0 = Bl[np][hf * 2], bl1 = Bl[np][hf * 2 + 1];
                        mma_bf16(acc[mt][nt], Ah[mt], bh0, bh1);  // hi*hi
                        mma_bf16(acc[mt][nt], Ah[mt], bl0, bl1);  // hi*lo
                        mma_bf16(acc[mt][nt], Al[mt], bh0, bh1);  // lo*hi
                    }
        }
    }

    // epilogue: C frag -> global
#pragma unroll
    for (int mt = 0; mt < 4; mt++) {
        int row0 = t0 + warp_m * 64 + mt * 16 + (lane >> 2);
#pragma unroll
        for (int nt = 0; nt < 4; nt++) {
            int col = d0 + warp_n * 32 + nt * 8 + (lane & 3) * 2;
            float* o0 = out + (size_t)(b * TSZ + row0) * DD + col;
            float* o1 = out + (size_t)(b * TSZ + row0 + 8) * DD + col;
            *(float2*)o0 = make_float2(acc[mt][nt][0], acc[mt][nt][1]);
            *(float2*)o1 = make_float2(acc[mt][nt][2], acc[mt][nt][3]);
        }
    }
}

extern "C" void kernel_launch(void* const* d_in, const int* in_sizes, int n_in,
                              void* d_out, int out_size) {
    const float* x = (const float*)d_in[0];
    const float* ec = (const float*)d_in[1];
    const float* W1 = (const float*)d_in[2];
    const float* b1 = (const float*)d_in[3];
    const float* W2 = (const float*)d_in[4];
    const float* b2 = (const float*)d_in[5];
    const float* W3 = (const float*)d_in[6];
    const float* b3 = (const float*)d_in[7];
    const float* wa = (const float*)d_in[8];
    // d_in[9] = wa_b: cancels in softmax -> unused.
    float* out = (float*)d_out;

    k0_w3e<<<1, 256>>>(ec, W3, b3);
    k1_proj<<<64, 256>>>(x, W1, b1, W2, b2);
    k2_scores<<<dim3(32, 32, 4), 256>>>(wa);
    k3_softmax<<<4096, 256>>>();
    k4_out_mma<<<dim3(4, 8, 4), 256>>>(x, out);
}